// round 14
// baseline (speedup 1.0000x reference)
#include <cuda_runtime.h>
#include <cuda_fp16.h>
#include <cstdint>

// MoEGate hybrid, fp16x3 (Ootomo-style split) tensor fast path + exact fixup.
//   prep: split W (scaled 2^6) into fp16 hi/lo arrays once per call; reset cnt.
//   fast (BM=64, BK=32, 256 thr, 8 warps, warp tile 32x16; 32KB smem -> 2-3
//     CTAs/SM co-resident, grid=256 all in one wave): logits = X @ W^T via f16
//     MMA (hi*hi + hi*lo + lo*hi, fp32 accumulate; X scaled 2^4, W 2^6; logits
//     unscaled by 2^-10 exactly). Pipeline: compute(t) overlaps cp.async W(t+1),
//     split+STS X(t+1), LDG X(t+2). top-9 gap check pushes ambiguous tokens
//     (adjacent gap < EPS) to g_list (order output-invariant).
//   fixup: ONE BLOCK PER DENSE TOKEN; exact sequential-k fp32 chains
//     (reference-matching order, proven R6/R8-R13) in one chain-wave.
// Output (float32): [T*8] topk weights, then [T*8] topk indices (as float).

#define H_DIM 2048
#define N_EXP 64
#define TOPK  8
#define BM    64
#define BK    32
#define KTILES (H_DIM / BK)       // 64
#define NTHREADS 256
#define EPS   2e-4f
#define SCALE_X 16.0f
#define SCALE_W 64.0f
#define ISCALE  (1.0f / 1024.0f)

// smem stage (halfs, 64B rows, SW64 swizzle)
#define ST_XHI 0
#define ST_XLO 4096
#define ST_WHI 8192
#define ST_WLO 12288
#define STAGE_BYTES 16384
#define SMEM_BYTES (2 * STAGE_BYTES)   // 32768

#define FIX_GRID 2048

__device__ int    g_list[FIX_GRID];
__device__ int    g_cnt;
__device__ __half g_whi[N_EXP * H_DIM];
__device__ __half g_wlo[N_EXP * H_DIM];

static __device__ __forceinline__ uint32_t smem_u32(const void* p) {
    uint32_t a;
    asm("{ .reg .u64 t; cvta.to.shared.u64 t, %1; cvt.u32.u64 %0, t; }" : "=r"(a) : "l"(p));
    return a;
}
static __device__ __forceinline__ uint32_t swz64(uint32_t off) {   // SW64 (64B rows)
    return off ^ ((off >> 3) & 0x30);
}
static __device__ __forceinline__ void sts16(uint32_t addr, uint4 v) {
    asm volatile("st.shared.v4.b32 [%0], {%1,%2,%3,%4};"
                 :: "r"(addr), "r"(v.x), "r"(v.y), "r"(v.z), "r"(v.w) : "memory");
}
static __device__ __forceinline__ void cp16(uint32_t dst, const void* src) {
    asm volatile("cp.async.cg.shared.global [%0], [%1], 16;" :: "r"(dst), "l"(src) : "memory");
}
static __device__ __forceinline__ void ldsm4(uint32_t r[4], uint32_t addr) {
    asm volatile("ldmatrix.sync.aligned.m8n8.x4.shared.b16 {%0,%1,%2,%3}, [%4];"
                 : "=r"(r[0]), "=r"(r[1]), "=r"(r[2]), "=r"(r[3]) : "r"(addr));
}
// packed split: hi = rn(f16x2 of s*x), lo = rn(f16x2 of s*x - hi)
static __device__ __forceinline__ void split4p(float4 v, float s, uint32_t& h01,
                                               uint32_t& h23, uint32_t& l01,
                                               uint32_t& l23) {
    float x0 = v.x * s, x1 = v.y * s, x2 = v.z * s, x3 = v.w * s;
    asm("cvt.rn.f16x2.f32 %0, %1, %2;" : "=r"(h01) : "f"(x1), "f"(x0));
    asm("cvt.rn.f16x2.f32 %0, %1, %2;" : "=r"(h23) : "f"(x3), "f"(x2));
    __half2 hh01 = *reinterpret_cast<__half2*>(&h01);
    __half2 hh23 = *reinterpret_cast<__half2*>(&h23);
    float f0 = __half2float(hh01.x), f1 = __half2float(hh01.y);
    float f2 = __half2float(hh23.x), f3 = __half2float(hh23.y);
    asm("cvt.rn.f16x2.f32 %0, %1, %2;" : "=r"(l01) : "f"(x1 - f1), "f"(x0 - f0));
    asm("cvt.rn.f16x2.f32 %0, %1, %2;" : "=r"(l23) : "f"(x3 - f3), "f"(x2 - f2));
}
static __device__ __forceinline__ void mma16(float c[4], const uint32_t a[4],
                                             const uint32_t b[2]) {
    asm volatile(
        "mma.sync.aligned.m16n8k16.row.col.f32.f16.f16.f32 "
        "{%0,%1,%2,%3}, {%4,%5,%6,%7}, {%8,%9}, {%0,%1,%2,%3};"
        : "+f"(c[0]), "+f"(c[1]), "+f"(c[2]), "+f"(c[3])
        : "r"(a[0]), "r"(a[1]), "r"(a[2]), "r"(a[3]), "r"(b[0]), "r"(b[1]));
}

__global__ __launch_bounds__(256, 4)
void moe_gate_prep(const float* __restrict__ W) {
    if (blockIdx.x == 0 && threadIdx.x == 0) g_cnt = 0;
    const int base = (blockIdx.x * 256 + threadIdx.x) * 8;
#pragma unroll
    for (int q = 0; q < 2; q++) {
        float4 v = *reinterpret_cast<const float4*>(W + base + 4 * q);
        uint32_t h01, h23, l01, l23;
        split4p(v, SCALE_W, h01, h23, l01, l23);
        *reinterpret_cast<uint2*>(&g_whi[base + 4 * q]) = make_uint2(h01, h23);
        *reinterpret_cast<uint2*>(&g_wlo[base + 4 * q]) = make_uint2(l01, l23);
    }
}

__global__ __launch_bounds__(NTHREADS, 3)
void moe_gate_fast(const float* __restrict__ X, const float* __restrict__ W,
                   float* __restrict__ out, int T) {
    extern __shared__ char smem_raw[];
    const uint32_t sbase = smem_u32(smem_raw);
    const int tid = threadIdx.x;
    const int block_m = blockIdx.x * BM;

    // ---- loader mapping ----
    const int xrow = tid >> 2, xk8 = (tid & 3) * 8;     // X: 8 floats/thread
    const int wexp = tid >> 2, wc8 = (tid & 3) * 8;     // W: 8 halves/thread per plane
    const float*  Xg  = X + (size_t)(block_m + xrow) * H_DIM + xk8;
    const __half* WgH = g_whi + (size_t)wexp * H_DIM + wc8;
    const __half* WgL = g_wlo + (size_t)wexp * H_DIM + wc8;
    const uint32_t xs0 = swz64((uint32_t)xrow * 64 + (uint32_t)xk8 * 2);
    const uint32_t wo  = swz64((uint32_t)wexp * 64 + (uint32_t)wc8 * 2);

    // ---- MMA mapping: 8 warps = 2(M) x 4(N), warp tile 32x16 ----
    const int wid = tid >> 5, lane = tid & 31;
    const int m0w = (wid & 1) * 32, n0w = (wid >> 1) * 16;
    const int gid = lane >> 2, tig = lane & 3;
    uint32_t a_base[2];
#pragma unroll
    for (int mt = 0; mt < 2; mt++)
        a_base[mt] = (uint32_t)(m0w + mt * 16 + (lane & 15)) * 64 + ((uint32_t)(lane >> 4) << 4);
    const uint32_t b_base =
        (uint32_t)(n0w + (lane & 7) + ((lane >> 3) & 1) * 8) * 64 + ((uint32_t)(lane >> 4) << 4);

    float acc[2][2][4];
#pragma unroll
    for (int mt = 0; mt < 2; mt++)
#pragma unroll
        for (int nf = 0; nf < 2; nf++)
#pragma unroll
            for (int r = 0; r < 4; r++) acc[mt][nf][r] = 0.f;

    float4 xbufA[2], xbufB[2];

    // ---- prologue: X(0)->regs->split->STS stage0 ; W(0) cp.async ; X(1)->regs
    xbufA[0] = *reinterpret_cast<const float4*>(Xg);
    xbufA[1] = *reinterpret_cast<const float4*>(Xg + 4);
    {
        cp16(sbase + ST_WHI + wo, WgH);
        cp16(sbase + ST_WLO + wo, WgL);
        asm volatile("cp.async.commit_group;" ::: "memory");
        uint32_t h01, h23, l01, l23, g01, g23, m01, m23;
        split4p(xbufA[0], SCALE_X, h01, h23, l01, l23);
        split4p(xbufA[1], SCALE_X, g01, g23, m01, m23);
        sts16(sbase + ST_XHI + xs0, make_uint4(h01, h23, g01, g23));
        sts16(sbase + ST_XLO + xs0, make_uint4(l01, l23, m01, m23));
    }
    xbufB[0] = *reinterpret_cast<const float4*>(Xg + BK);
    xbufB[1] = *reinterpret_cast<const float4*>(Xg + BK + 4);
    asm volatile("cp.async.wait_group 0;" ::: "memory");
    __syncthreads();

    // ---- pipelined main loop ----
    auto tile = [&](int t, float4* xsplit, float4* xload) {
        const uint32_t sb  = sbase + (uint32_t)(t & 1) * STAGE_BYTES;
        const uint32_t sb2 = sbase + (uint32_t)((t + 1) & 1) * STAGE_BYTES;
        const bool has1 = (t + 1 < KTILES);
        const bool has2 = (t + 2 < KTILES);

        if (has1) {
            cp16(sb2 + ST_WHI + wo, WgH + (t + 1) * BK);
            cp16(sb2 + ST_WLO + wo, WgL + (t + 1) * BK);
        }
        asm volatile("cp.async.commit_group;" ::: "memory");

#pragma unroll
        for (int s = 0; s < 2; s++) {
            const uint32_t ko = (uint32_t)s * 32;
            uint32_t ahi[2][4], alo[2][4], bhi[2][2], blo[2][2], r[4];
#pragma unroll
            for (int mt = 0; mt < 2; mt++) {
                ldsm4(ahi[mt], sb + ST_XHI + swz64(a_base[mt] + ko));
                ldsm4(alo[mt], sb + ST_XLO + swz64(a_base[mt] + ko));
            }
            ldsm4(r, sb + ST_WHI + swz64(b_base + ko));
            bhi[0][0] = r[0]; bhi[0][1] = r[2];
            bhi[1][0] = r[1]; bhi[1][1] = r[3];
            ldsm4(r, sb + ST_WLO + swz64(b_base + ko));
            blo[0][0] = r[0]; blo[0][1] = r[2];
            blo[1][0] = r[1]; blo[1][1] = r[3];

            // next-tile work hidden under the MMAs below
            if (s == 0 && has1) {
                uint32_t h01, h23, l01, l23, g01, g23, m01, m23;
                split4p(xsplit[0], SCALE_X, h01, h23, l01, l23);
                split4p(xsplit[1], SCALE_X, g01, g23, m01, m23);
                sts16(sb2 + ST_XHI + xs0, make_uint4(h01, h23, g01, g23));
                sts16(sb2 + ST_XLO + xs0, make_uint4(l01, l23, m01, m23));
            }
            if (s == 1 && has2) {
                const float* xg = Xg + (t + 2) * BK;
                xload[0] = *reinterpret_cast<const float4*>(xg);
                xload[1] = *reinterpret_cast<const float4*>(xg + 4);
            }

#pragma unroll
            for (int mt = 0; mt < 2; mt++)
#pragma unroll
                for (int nf = 0; nf < 2; nf++) {
                    mma16(acc[mt][nf], ahi[mt], bhi[nf]);   // hi*hi
                    mma16(acc[mt][nf], ahi[mt], blo[nf]);   // hi*lo
                    mma16(acc[mt][nf], alo[mt], bhi[nf]);   // lo*hi
                }
        }
        asm volatile("cp.async.wait_group 0;" ::: "memory");
        __syncthreads();
    };

    for (int t = 0; t < KTILES; t += 2) {
        tile(t,     xbufB, xbufA);
        tile(t + 1, xbufA, xbufB);
    }

    // logits[64][66] in smem (unscale by 2^-10)
    float* lg = reinterpret_cast<float*>(smem_raw);
#pragma unroll
    for (int mt = 0; mt < 2; mt++)
#pragma unroll
        for (int nf = 0; nf < 2; nf++) {
            const int col = n0w + nf * 8 + 2 * tig;
            const int row = m0w + mt * 16 + gid;
            *reinterpret_cast<float2*>(lg + row * 66 + col) =
                make_float2(acc[mt][nf][0] * ISCALE, acc[mt][nf][1] * ISCALE);
            *reinterpret_cast<float2*>(lg + (row + 8) * 66 + col) =
                make_float2(acc[mt][nf][2] * ISCALE, acc[mt][nf][3] * ISCALE);
        }
    __syncthreads();

    if (tid < BM) {
        float* row = lg + tid * 66;
        float vals[TOPK + 1];
        int   idxs[TOPK + 1];
#pragma unroll
        for (int r = 0; r < TOPK + 1; r++) {      // top-9 for gap check
            float best = -__int_as_float(0x7f800000);
            int bi = 0;
            for (int e = 0; e < N_EXP; e++) {
                float v = row[e];
                if (v > best) { best = v; bi = e; }
            }
            vals[r] = best;
            idxs[r] = bi;
            row[bi] = -__int_as_float(0x7f800000);
        }
        float mingap = vals[0] - vals[1];
#pragma unroll
        for (int r = 1; r < TOPK; r++) mingap = fminf(mingap, vals[r] - vals[r + 1]);

        const long long gtok = block_m + tid;
        if (mingap < EPS) {
            int pos = atomicAdd(&g_cnt, 1);
            if (pos < FIX_GRID) g_list[pos] = (int)gtok;
        }

        const float m0f = vals[0];
        float wv[TOPK];
        float s = 0.f;
#pragma unroll
        for (int r = 0; r < TOPK; r++) { wv[r] = __expf(vals[r] - m0f); s += wv[r]; }
        const float inv = 1.f / s;
#pragma unroll
        for (int r = 0; r < TOPK; r++) {
            out[gtok * TOPK + r] = wv[r] * inv;
            out[(long long)T * TOPK + gtok * TOPK + r] = (float)idxs[r];
        }
    }
}

// exact slow path: one block per dense token; all chains in ONE wave.
__global__ __launch_bounds__(64, 4)
void moe_gate_fixup(const float* __restrict__ X, const float* __restrict__ W,
                    float* __restrict__ out, int T) {
    __shared__ float xs[H_DIM];
    __shared__ float lg[N_EXP];
    const int n = g_cnt < FIX_GRID ? g_cnt : FIX_GRID;
    if (blockIdx.x >= n) return;
    const int tok = g_list[blockIdx.x];

    const int e = threadIdx.x;
    {
        const float4* xg = reinterpret_cast<const float4*>(X + (size_t)tok * H_DIM);
        float4* xd = reinterpret_cast<float4*>(xs);
#pragma unroll
        for (int i = 0; i < H_DIM / 4 / 64; i++) xd[e + i * 64] = xg[e + i * 64];
    }
    __syncthreads();

    float acc = 0.f;
    float4 bufA[16], bufB[16];
    const float4* w4 = reinterpret_cast<const float4*>(W + (size_t)e * H_DIM);
#pragma unroll
    for (int j = 0; j < 16; j++) bufA[j] = w4[j];

    for (int c = 0; c < 32; c += 2) {
        if (c + 1 < 32) {
#pragma unroll
            for (int j = 0; j < 16; j++) bufB[j] = w4[(c + 1) * 16 + j];
        }
        const float4* xc = reinterpret_cast<const float4*>(xs + c * 64);
#pragma unroll
        for (int j = 0; j < 16; j++) {       // strict sequential chain
            float4 xv = xc[j];
            acc = fmaf(xv.x, bufA[j].x, acc);
            acc = fmaf(xv.y, bufA[j].y, acc);
            acc = fmaf(xv.z, bufA[j].z, acc);
            acc = fmaf(xv.w, bufA[j].w, acc);
        }
        if (c + 2 < 32) {
#pragma unroll
            for (int j = 0; j < 16; j++) bufA[j] = w4[(c + 2) * 16 + j];
        }
        const float4* xc2 = reinterpret_cast<const float4*>(xs + (c + 1) * 64);
#pragma unroll
        for (int j = 0; j < 16; j++) {
            float4 xv = xc2[j];
            acc = fmaf(xv.x, bufB[j].x, acc);
            acc = fmaf(xv.y, bufB[j].y, acc);
            acc = fmaf(xv.z, bufB[j].z, acc);
            acc = fmaf(xv.w, bufB[j].w, acc);
        }
    }
    lg[e] = acc;
    __syncthreads();

    if (e == 0) {
        float vals[TOPK];
        int   idxs[TOPK];
#pragma unroll
        for (int r = 0; r < TOPK; r++) {
            float best = -__int_as_float(0x7f800000);
            int bi = 0;
            for (int q = 0; q < N_EXP; q++) {
                float v = lg[q];
                if (v > best) { best = v; bi = q; }
            }
            vals[r] = best;
            idxs[r] = bi;
            lg[bi] = -__int_as_float(0x7f800000);
        }
        const float m0f = vals[0];
        float wv[TOPK];
        float sm = 0.f;
#pragma unroll
        for (int r = 0; r < TOPK; r++) { wv[r] = __expf(vals[r] - m0f); sm += wv[r]; }
        const float inv = 1.f / sm;
#pragma unroll
        for (int r = 0; r < TOPK; r++) {
            out[(long long)tok * TOPK + r] = wv[r] * inv;
            out[(long long)T * TOPK + (long long)tok * TOPK + r] = (float)idxs[r];
        }
    }
}

extern "C" void kernel_launch(void* const* d_in, const int* in_sizes, int n_in,
                              void* d_out, int out_size) {
    const float* X = (const float*)d_in[0];   // hidden_states [4,4096,2048] fp32
    const float* W = (const float*)d_in[1];   // weight [64,2048] fp32
    float* out = (float*)d_out;

    const int T = in_sizes[0] / H_DIM;        // 16384
    const int grid = T / BM;                  // 256

    cudaFuncSetAttribute(moe_gate_fast,
                         cudaFuncAttributeMaxDynamicSharedMemorySize, SMEM_BYTES);
    moe_gate_prep<<<(N_EXP * H_DIM) / (256 * 8), 256>>>(W);
    moe_gate_fast<<<grid, NTHREADS, SMEM_BYTES>>>(X, W, out, T);
    moe_gate_fixup<<<FIX_GRID, 64>>>(X, W, out, T);
}

// round 15
// speedup vs baseline: 1.1464x; 1.1464x over previous
#include <cuda_runtime.h>
#include <cuda_fp16.h>
#include <cstdint>

// MoEGate hybrid, fp16x3 (Ootomo-style split) tensor fast path + exact fixup.
//   prep: split W (scaled 2^6) into fp16 hi/lo arrays once per call; reset cnt.
//   fast (512 thr, 16 warps, warp tile 32x16, BK=64, software-pipelined):
//     compute(t) overlaps cp.async W(t+1), split+STS X(t+1), LDG X(t+2).
//     MMA stream is TERM-MAJOR (all accs' hi*hi, then hi*lo, then lo*hi) so
//     dependent MMAs on the same accumulator are separated by 4 independent
//     ones; per-acc accumulation order (hh->hl->lh) is unchanged -> logits
//     bit-identical to R12/R13. X scaled 2^4, W 2^6; logits unscaled 2^-10.
//     top-9 gap check pushes ambiguous tokens (gap < EPS) to g_list.
//   fixup: ONE BLOCK PER DENSE TOKEN; exact sequential-k fp32 chains
//     (reference-matching order, proven R6/R8-R13) in one chain-wave.
// Output (float32): [T*8] topk weights, then [T*8] topk indices (as float).

#define H_DIM 2048
#define N_EXP 64
#define TOPK  8
#define BM    128
#define BK    64
#define KTILES (H_DIM / BK)       // 32
#define NTHREADS 512
#define EPS   2e-4f
#define SCALE_X 16.0f
#define SCALE_W 64.0f
#define ISCALE  (1.0f / 1024.0f)

// smem stage (halfs, 128B rows, SW128 swizzle)
#define ST_XHI 0
#define ST_XLO 16384
#define ST_WHI 32768
#define ST_WLO 40960
#define STAGE_BYTES 49152
#define SMEM_BYTES (2 * STAGE_BYTES)   // 98304

#define FIX_GRID 2048

__device__ int    g_list[FIX_GRID];
__device__ int    g_cnt;
__device__ __half g_whi[N_EXP * H_DIM];
__device__ __half g_wlo[N_EXP * H_DIM];

static __device__ __forceinline__ uint32_t smem_u32(const void* p) {
    uint32_t a;
    asm("{ .reg .u64 t; cvta.to.shared.u64 t, %1; cvt.u32.u64 %0, t; }" : "=r"(a) : "l"(p));
    return a;
}
static __device__ __forceinline__ uint32_t swz(uint32_t off) {   // SW128
    return off ^ ((off >> 3) & 0x70);
}
static __device__ __forceinline__ void sts16(uint32_t addr, uint4 v) {
    asm volatile("st.shared.v4.b32 [%0], {%1,%2,%3,%4};"
                 :: "r"(addr), "r"(v.x), "r"(v.y), "r"(v.z), "r"(v.w) : "memory");
}
static __device__ __forceinline__ void cp16(uint32_t dst, const void* src) {
    asm volatile("cp.async.cg.shared.global [%0], [%1], 16;" :: "r"(dst), "l"(src) : "memory");
}
static __device__ __forceinline__ void ldsm4(uint32_t r[4], uint32_t addr) {
    asm volatile("ldmatrix.sync.aligned.m8n8.x4.shared.b16 {%0,%1,%2,%3}, [%4];"
                 : "=r"(r[0]), "=r"(r[1]), "=r"(r[2]), "=r"(r[3]) : "r"(addr));
}
// packed split: hi = rn(f16x2 of s*x), lo = rn(f16x2 of s*x - hi)
static __device__ __forceinline__ void split4p(float4 v, float s, uint32_t& h01,
                                               uint32_t& h23, uint32_t& l01,
                                               uint32_t& l23) {
    float x0 = v.x * s, x1 = v.y * s, x2 = v.z * s, x3 = v.w * s;
    asm("cvt.rn.f16x2.f32 %0, %1, %2;" : "=r"(h01) : "f"(x1), "f"(x0));
    asm("cvt.rn.f16x2.f32 %0, %1, %2;" : "=r"(h23) : "f"(x3), "f"(x2));
    __half2 hh01 = *reinterpret_cast<__half2*>(&h01);
    __half2 hh23 = *reinterpret_cast<__half2*>(&h23);
    float f0 = __half2float(hh01.x), f1 = __half2float(hh01.y);
    float f2 = __half2float(hh23.x), f3 = __half2float(hh23.y);
    asm("cvt.rn.f16x2.f32 %0, %1, %2;" : "=r"(l01) : "f"(x1 - f1), "f"(x0 - f0));
    asm("cvt.rn.f16x2.f32 %0, %1, %2;" : "=r"(l23) : "f"(x3 - f3), "f"(x2 - f2));
}
static __device__ __forceinline__ void mma16(float c[4], const uint32_t a[4],
                                             const uint32_t b[2]) {
    asm volatile(
        "mma.sync.aligned.m16n8k16.row.col.f32.f16.f16.f32 "
        "{%0,%1,%2,%3}, {%4,%5,%6,%7}, {%8,%9}, {%0,%1,%2,%3};"
        : "+f"(c[0]), "+f"(c[1]), "+f"(c[2]), "+f"(c[3])
        : "r"(a[0]), "r"(a[1]), "r"(a[2]), "r"(a[3]), "r"(b[0]), "r"(b[1]));
}

__global__ __launch_bounds__(256, 4)
void moe_gate_prep(const float* __restrict__ W) {
    if (blockIdx.x == 0 && threadIdx.x == 0) g_cnt = 0;
    const int base = (blockIdx.x * 256 + threadIdx.x) * 8;
#pragma unroll
    for (int q = 0; q < 2; q++) {
        float4 v = *reinterpret_cast<const float4*>(W + base + 4 * q);
        uint32_t h01, h23, l01, l23;
        split4p(v, SCALE_W, h01, h23, l01, l23);
        *reinterpret_cast<uint2*>(&g_whi[base + 4 * q]) = make_uint2(h01, h23);
        *reinterpret_cast<uint2*>(&g_wlo[base + 4 * q]) = make_uint2(l01, l23);
    }
}

__global__ __launch_bounds__(NTHREADS, 1)
void moe_gate_fast(const float* __restrict__ X, const float* __restrict__ W,
                   float* __restrict__ out, int T) {
    extern __shared__ char smem_raw[];
    const uint32_t sbase = smem_u32(smem_raw);
    const int tid = threadIdx.x;
    const int block_m = blockIdx.x * BM;

    // ---- loader mapping ----
    const int xrow = tid >> 2, xk16 = (tid & 3) * 16;
    const int wrow = tid >> 3, wk8  = (tid & 7) * 8;
    const float*  Xg  = X + (size_t)(block_m + xrow) * H_DIM + xk16;
    const __half* WgH = g_whi + (size_t)wrow * H_DIM + wk8;
    const __half* WgL = g_wlo + (size_t)wrow * H_DIM + wk8;
    const uint32_t xo  = (uint32_t)xrow * 128 + (uint32_t)xk16 * 2;
    const uint32_t xs0 = swz(xo), xs1 = swz(xo + 16);
    const uint32_t wo  = swz((uint32_t)wrow * 128 + (uint32_t)wk8 * 2);

    // ---- MMA mapping: 16 warps = 4(M) x 4(N), warp tile 32x16 ----
    const int wid = tid >> 5, lane = tid & 31;
    const int m0w = (wid & 3) * 32, n0w = (wid >> 2) * 16;
    const int gid = lane >> 2, tig = lane & 3;
    uint32_t a_base[2];
#pragma unroll
    for (int mt = 0; mt < 2; mt++)
        a_base[mt] = (uint32_t)(m0w + mt * 16 + (lane & 15)) * 128 + ((uint32_t)(lane >> 4) << 4);
    const uint32_t b_base =
        (uint32_t)(n0w + (lane & 7) + ((lane >> 3) & 1) * 8) * 128 + ((uint32_t)(lane >> 4) << 4);

    float acc[2][2][4];
#pragma unroll
    for (int mt = 0; mt < 2; mt++)
#pragma unroll
        for (int nf = 0; nf < 2; nf++)
#pragma unroll
            for (int r = 0; r < 4; r++) acc[mt][nf][r] = 0.f;

    float4 xbufA[4], xbufB[4];

    // ---- prologue ----
#pragma unroll
    for (int q = 0; q < 4; q++) xbufA[q] = *reinterpret_cast<const float4*>(Xg + 4 * q);
    {
        const uint32_t sb = sbase;
        cp16(sb + ST_WHI + wo, WgH);
        cp16(sb + ST_WLO + wo, WgL);
        asm volatile("cp.async.commit_group;" ::: "memory");
        uint32_t h01, h23, l01, l23, g01, g23, m01, m23;
        split4p(xbufA[0], SCALE_X, h01, h23, l01, l23);
        split4p(xbufA[1], SCALE_X, g01, g23, m01, m23);
        sts16(sb + ST_XHI + xs0, make_uint4(h01, h23, g01, g23));
        sts16(sb + ST_XLO + xs0, make_uint4(l01, l23, m01, m23));
        split4p(xbufA[2], SCALE_X, h01, h23, l01, l23);
        split4p(xbufA[3], SCALE_X, g01, g23, m01, m23);
        sts16(sb + ST_XHI + xs1, make_uint4(h01, h23, g01, g23));
        sts16(sb + ST_XLO + xs1, make_uint4(l01, l23, m01, m23));
    }
#pragma unroll
    for (int q = 0; q < 4; q++) xbufB[q] = *reinterpret_cast<const float4*>(Xg + BK + 4 * q);
    asm volatile("cp.async.wait_group 0;" ::: "memory");
    __syncthreads();

    // ---- pipelined main loop ----
    auto tile = [&](int t, float4* xsplit, float4* xload) {
        const uint32_t sb  = sbase + (uint32_t)(t & 1) * STAGE_BYTES;
        const uint32_t sb2 = sbase + (uint32_t)((t + 1) & 1) * STAGE_BYTES;
        const bool has1 = (t + 1 < KTILES);
        const bool has2 = (t + 2 < KTILES);

        if (has1) {
            cp16(sb2 + ST_WHI + wo, WgH + (t + 1) * BK);
            cp16(sb2 + ST_WLO + wo, WgL + (t + 1) * BK);
        }
        asm volatile("cp.async.commit_group;" ::: "memory");

#pragma unroll
        for (int s = 0; s < 4; s++) {
            const uint32_t ko = (uint32_t)s * 32;
            uint32_t ahi[2][4], alo[2][4], bhi[2][2], blo[2][2], r[4];
#pragma unroll
            for (int mt = 0; mt < 2; mt++) {
                ldsm4(ahi[mt], sb + ST_XHI + swz(a_base[mt] + ko));
                ldsm4(alo[mt], sb + ST_XLO + swz(a_base[mt] + ko));
            }
            ldsm4(r, sb + ST_WHI + swz(b_base + ko));
            bhi[0][0] = r[0]; bhi[0][1] = r[2];
            bhi[1][0] = r[1]; bhi[1][1] = r[3];
            ldsm4(r, sb + ST_WLO + swz(b_base + ko));
            blo[0][0] = r[0]; blo[0][1] = r[2];
            blo[1][0] = r[1]; blo[1][1] = r[3];

            // interleaved next-tile work (hidden under the MMAs below)
            if (s == 0 && has1) {
                uint32_t h01, h23, l01, l23, g01, g23, m01, m23;
                split4p(xsplit[0], SCALE_X, h01, h23, l01, l23);
                split4p(xsplit[1], SCALE_X, g01, g23, m01, m23);
                sts16(sb2 + ST_XHI + xs0, make_uint4(h01, h23, g01, g23));
                sts16(sb2 + ST_XLO + xs0, make_uint4(l01, l23, m01, m23));
            }
            if (s == 1 && has1) {
                uint32_t h01, h23, l01, l23, g01, g23, m01, m23;
                split4p(xsplit[2], SCALE_X, h01, h23, l01, l23);
                split4p(xsplit[3], SCALE_X, g01, g23, m01, m23);
                sts16(sb2 + ST_XHI + xs1, make_uint4(h01, h23, g01, g23));
                sts16(sb2 + ST_XLO + xs1, make_uint4(l01, l23, m01, m23));
            }
            if (s == 2 && has2) {
                const float* xg = Xg + (t + 2) * BK;
                xload[0] = *reinterpret_cast<const float4*>(xg);
                xload[1] = *reinterpret_cast<const float4*>(xg + 4);
            }
            if (s == 3 && has2) {
                const float* xg = Xg + (t + 2) * BK;
                xload[2] = *reinterpret_cast<const float4*>(xg + 8);
                xload[3] = *reinterpret_cast<const float4*>(xg + 12);
            }

            // TERM-MAJOR MMA stream: 4 independent MMAs between each dependent
            // pair on the same accumulator; per-acc order stays hh -> hl -> lh
            // (bit-identical accumulation vs acc-major).
#pragma unroll
            for (int mt = 0; mt < 2; mt++)
#pragma unroll
                for (int nf = 0; nf < 2; nf++)
                    mma16(acc[mt][nf], ahi[mt], bhi[nf]);   // hi*hi
#pragma unroll
            for (int mt = 0; mt < 2; mt++)
#pragma unroll
                for (int nf = 0; nf < 2; nf++)
                    mma16(acc[mt][nf], ahi[mt], blo[nf]);   // hi*lo
#pragma unroll
            for (int mt = 0; mt < 2; mt++)
#pragma unroll
                for (int nf = 0; nf < 2; nf++)
                    mma16(acc[mt][nf], alo[mt], bhi[nf]);   // lo*hi
        }
        asm volatile("cp.async.wait_group 0;" ::: "memory");
        __syncthreads();
    };

    for (int t = 0; t < KTILES; t += 2) {
        tile(t,     xbufB, xbufA);
        tile(t + 1, xbufA, xbufB);
    }

    // logits[128][66] in smem (unscale by 2^-10)
    float* lg = reinterpret_cast<float*>(smem_raw);
#pragma unroll
    for (int mt = 0; mt < 2; mt++)
#pragma unroll
        for (int nf = 0; nf < 2; nf++) {
            const int col = n0w + nf * 8 + 2 * tig;
            const int row = m0w + mt * 16 + gid;
            *reinterpret_cast<float2*>(lg + row * 66 + col) =
                make_float2(acc[mt][nf][0] * ISCALE, acc[mt][nf][1] * ISCALE);
            *reinterpret_cast<float2*>(lg + (row + 8) * 66 + col) =
                make_float2(acc[mt][nf][2] * ISCALE, acc[mt][nf][3] * ISCALE);
        }
    __syncthreads();

    if (tid < BM) {
        float* row = lg + tid * 66;
        float vals[TOPK + 1];
        int   idxs[TOPK + 1];
#pragma unroll
        for (int r = 0; r < TOPK + 1; r++) {      // top-9 for gap check
            float best = -__int_as_float(0x7f800000);
            int bi = 0;
            for (int e = 0; e < N_EXP; e++) {
                float v = row[e];
                if (v > best) { best = v; bi = e; }
            }
            vals[r] = best;
            idxs[r] = bi;
            row[bi] = -__int_as_float(0x7f800000);
        }
        float mingap = vals[0] - vals[1];
#pragma unroll
        for (int r = 1; r < TOPK; r++) mingap = fminf(mingap, vals[r] - vals[r + 1]);

        const long long gtok = block_m + tid;
        if (mingap < EPS) {
            int pos = atomicAdd(&g_cnt, 1);
            if (pos < FIX_GRID) g_list[pos] = (int)gtok;
        }

        const float m0f = vals[0];
        float wv[TOPK];
        float s = 0.f;
#pragma unroll
        for (int r = 0; r < TOPK; r++) { wv[r] = __expf(vals[r] - m0f); s += wv[r]; }
        const float inv = 1.f / s;
#pragma unroll
        for (int r = 0; r < TOPK; r++) {
            out[gtok * TOPK + r] = wv[r] * inv;
            out[(long long)T * TOPK + gtok * TOPK + r] = (float)idxs[r];
        }
    }
}

// exact slow path: one block per dense token; all chains in ONE wave.
__global__ __launch_bounds__(64, 4)
void moe_gate_fixup(const float* __restrict__ X, const float* __restrict__ W,
                    float* __restrict__ out, int T) {
    __shared__ float xs[H_DIM];
    __shared__ float lg[N_EXP];
    const int n = g_cnt < FIX_GRID ? g_cnt : FIX_GRID;
    if (blockIdx.x >= n) return;
    const int tok = g_list[blockIdx.x];

    const int e = threadIdx.x;
    {
        const float4* xg = reinterpret_cast<const float4*>(X + (size_t)tok * H_DIM);
        float4* xd = reinterpret_cast<float4*>(xs);
#pragma unroll
        for (int i = 0; i < H_DIM / 4 / 64; i++) xd[e + i * 64] = xg[e + i * 64];
    }
    __syncthreads();

    float acc = 0.f;
    float4 bufA[16], bufB[16];
    const float4* w4 = reinterpret_cast<const float4*>(W + (size_t)e * H_DIM);
#pragma unroll
    for (int j = 0; j < 16; j++) bufA[j] = w4[j];

    for (int c = 0; c < 32; c += 2) {
        if (c + 1 < 32) {
#pragma unroll
            for (int j = 0; j < 16; j++) bufB[j] = w4[(c + 1) * 16 + j];
        }
        const float4* xc = reinterpret_cast<const float4*>(xs + c * 64);
#pragma unroll
        for (int j = 0; j < 16; j++) {       // strict sequential chain
            float4 xv = xc[j];
            acc = fmaf(xv.x, bufA[j].x, acc);
            acc = fmaf(xv.y, bufA[j].y, acc);
            acc = fmaf(xv.z, bufA[j].z, acc);
            acc = fmaf(xv.w, bufA[j].w, acc);
        }
        if (c + 2 < 32) {
#pragma unroll
            for (int j = 0; j < 16; j++) bufA[j] = w4[(c + 2) * 16 + j];
        }
        const float4* xc2 = reinterpret_cast<const float4*>(xs + (c + 1) * 64);
#pragma unroll
        for (int j = 0; j < 16; j++) {
            float4 xv = xc2[j];
            acc = fmaf(xv.x, bufB[j].x, acc);
            acc = fmaf(xv.y, bufB[j].y, acc);
            acc = fmaf(xv.z, bufB[j].z, acc);
            acc = fmaf(xv.w, bufB[j].w, acc);
        }
    }
    lg[e] = acc;
    __syncthreads();

    if (e == 0) {
        float vals[TOPK];
        int   idxs[TOPK];
#pragma unroll
        for (int r = 0; r < TOPK; r++) {
            float best = -__int_as_float(0x7f800000);
            int bi = 0;
            for (int q = 0; q < N_EXP; q++) {
                float v = lg[q];
                if (v > best) { best = v; bi = q; }
            }
            vals[r] = best;
            idxs[r] = bi;
            lg[bi] = -__int_as_float(0x7f800000);
        }
        const float m0f = vals[0];
        float wv[TOPK];
        float sm = 0.f;
#pragma unroll
        for (int r = 0; r < TOPK; r++) { wv[r] = __expf(vals[r] - m0f); sm += wv[r]; }
        const float inv = 1.f / sm;
#pragma unroll
        for (int r = 0; r < TOPK; r++) {
            out[(long long)tok * TOPK + r] = wv[r] * inv;
            out[(long long)T * TOPK + (long long)tok * TOPK + r] = (float)idxs[r];
        }
    }
}

extern "C" void kernel_launch(void* const* d_in, const int* in_sizes, int n_in,
                              void* d_out, int out_size) {
    const float* X = (const float*)d_in[0];   // hidden_states [4,4096,2048] fp32
    const float* W = (const float*)d_in[1];   // weight [64,2048] fp32
    float* out = (float*)d_out;

    const int T = in_sizes[0] / H_DIM;        // 16384
    const int grid = T / BM;                  // 128

    cudaFuncSetAttribute(moe_gate_fast,
                         cudaFuncAttributeMaxDynamicSharedMemorySize, SMEM_BYTES);
    moe_gate_prep<<<(N_EXP * H_DIM) / (256 * 8), 256>>>(W);
    moe_gate_fast<<<grid, NTHREADS, SMEM_BYTES>>>(X, W, out, T);
    moe_gate_fixup<<<FIX_GRID, 64>>>(X, W, out, T);
}